// round 9
// baseline (speedup 1.0000x reference)
#include <cuda_runtime.h>
#include <cuda_fp16.h>
#include <math.h>
#include <stdint.h>

// Problem shape (fixed): N=8, C=128, H=W=32 -> HW=1024.
#define NB   8
#define CC   128
#define HW   1024
#define BM   128
#define BN   128
#define BK   32            // K-chunk (4 chunks of 32 = CC)
#define NCHUNK (CC / BK)   // 4

#define NPIX (NB * HW)     // 8192
#define RBLK 64            // reduce grid

// ---------------------------------------------------------------------------
// Device scratch — zero-initialized at load; reduce_kernel restores zeros
// after each use so every call sees a clean state (deterministic).
// ---------------------------------------------------------------------------
__device__ float g_rowL [NPIX];
__device__ float g_rowLM[NPIX];
__device__ float g_colL [NPIX];
__device__ float g_colLM[NPIX];
__device__ float g_tot;
__device__ float g_cnt;
__device__ unsigned int g_rctr;

// ---------------------------------------------------------------------------
// PTX helpers
// ---------------------------------------------------------------------------
__device__ __forceinline__ uint32_t smem_u32(const void* p) {
    return (uint32_t)__cvta_generic_to_shared(p);
}

__device__ __forceinline__ void ldsm_x4_t(uint32_t& r0, uint32_t& r1,
                                          uint32_t& r2, uint32_t& r3, uint32_t addr) {
    asm volatile("ldmatrix.sync.aligned.m8n8.x4.trans.shared.b16 {%0,%1,%2,%3}, [%4];"
                 : "=r"(r0), "=r"(r1), "=r"(r2), "=r"(r3) : "r"(addr));
}

__device__ __forceinline__ void ldsm_x2_t(uint32_t& r0, uint32_t& r1, uint32_t addr) {
    asm volatile("ldmatrix.sync.aligned.m8n8.x2.trans.shared.b16 {%0,%1}, [%2];"
                 : "=r"(r0), "=r"(r1) : "r"(addr));
}

// f16 inputs, f16 accumulators (halves register pressure vs f32 accum).
__device__ __forceinline__ void mma_f16(uint32_t& d0, uint32_t& d1,
                                        uint32_t a0, uint32_t a1, uint32_t a2, uint32_t a3,
                                        uint32_t b0, uint32_t b1) {
    asm volatile("mma.sync.aligned.m16n8k16.row.col.f16.f16.f16.f16 "
                 "{%0,%1}, {%2,%3,%4,%5}, {%6,%7}, {%0,%1};"
                 : "+r"(d0), "+r"(d1)
                 : "r"(a0), "r"(a1), "r"(a2), "r"(a3), "r"(b0), "r"(b1));
}

// ---------------------------------------------------------------------------
// Fully fused tile kernel: fp32 load -> f16 convert -> tensor-core GEMM ->
// epilogue. Norms computed in-CTA from the fp32 values (exact). One smem
// tile buffer; overlap comes from register-staged LDG prefetch of chunk c+1
// during the mma of chunk c.
// ---------------------------------------------------------------------------
__global__ __launch_bounds__(256, 2)
void tile_kernel(const float* __restrict__ R, const float* __restrict__ I,
                 const int* __restrict__ RM, const int* __restrict__ IM)
{
    // smem: tile buffers (17408 B) reused after the mainloop as the norm
    // reduction scratch (9216 B).
    __shared__ __align__(16) char s_buf[2 * 32 * 136 * 2];
    __half (*As)[136] = reinterpret_cast<__half(*)[136]>(s_buf);
    __half (*Bs)[136] = reinterpret_cast<__half(*)[136]>(s_buf + 32 * 136 * 2);
    float  (*nred)[9] = reinterpret_cast<float(*)[9]>(s_buf);   // [256][9]
    __shared__ float s_normA[128];
    __shared__ float s_normB[128];

    const int n  = blockIdx.z;
    const int p0 = blockIdx.y * BM;
    const int q0 = blockIdx.x * BN;
    const int tid  = threadIdx.x;
    const int wid  = tid >> 5;
    const int lane = tid & 31;
    const int warp_m = wid >> 2;   // 0..1
    const int warp_n = wid & 3;    // 0..3

    // Staging decomposition: thread covers rows {m, m+8, m+16, m+24} of each
    // 32-row chunk, pixel group g32*4..+3. fp32 loads are float4, coalesced.
    const int mrow = tid >> 5;     // 0..7
    const int g32  = tid & 31;     // pixel group (4 px)
    const float* Ra = R + n * CC * HW + p0 + g32 * 4;
    const float* Ia = I + n * CC * HW + q0 + g32 * 4;

    float4 fA[4], fB[4];
    auto ldg_chunk = [&](int c) {
        #pragma unroll
        for (int k = 0; k < 4; k++) {
            int row = c * BK + mrow + k * 8;
            fA[k] = *reinterpret_cast<const float4*>(Ra + row * HW);
            fB[k] = *reinterpret_cast<const float4*>(Ia + row * HW);
        }
    };

    uint32_t acc[4][4][2];
    #pragma unroll
    for (int mi = 0; mi < 4; mi++)
        #pragma unroll
        for (int ni = 0; ni < 4; ni++) {
            acc[mi][ni][0] = 0u; acc[mi][ni][1] = 0u;
        }

    // ldmatrix lane decomposition
    const int sub   = lane >> 3;
    const int lrow  = lane & 7;
    const int a_kad = lrow + ((sub >> 1) ? 8 : 0);
    const int a_mad = warp_m * 64 + ((sub & 1) ? 8 : 0);
    const int b_kad = lrow + (((lane >> 3) & 1) ? 8 : 0);

    float npA[4] = {0.f, 0.f, 0.f, 0.f};
    float npB[4] = {0.f, 0.f, 0.f, 0.f};

    ldg_chunk(0);

    #pragma unroll
    for (int c = 0; c < NCHUNK; c++) {
        // Convert chunk c (in regs) -> f16 smem; accumulate fp32 norms.
        #pragma unroll
        for (int k = 0; k < 4; k++) {
            int row = mrow + k * 8;
            float4 v = fA[k];
            npA[0] = fmaf(v.x, v.x, npA[0]);
            npA[1] = fmaf(v.y, v.y, npA[1]);
            npA[2] = fmaf(v.z, v.z, npA[2]);
            npA[3] = fmaf(v.w, v.w, npA[3]);
            __half2 h0 = __floats2half2_rn(v.x, v.y);
            __half2 h1 = __floats2half2_rn(v.z, v.w);
            uint2 u;
            u.x = *reinterpret_cast<uint32_t*>(&h0);
            u.y = *reinterpret_cast<uint32_t*>(&h1);
            *reinterpret_cast<uint2*>(&As[row][g32 * 4]) = u;

            float4 w = fB[k];
            npB[0] = fmaf(w.x, w.x, npB[0]);
            npB[1] = fmaf(w.y, w.y, npB[1]);
            npB[2] = fmaf(w.z, w.z, npB[2]);
            npB[3] = fmaf(w.w, w.w, npB[3]);
            __half2 g0 = __floats2half2_rn(w.x, w.y);
            __half2 g1 = __floats2half2_rn(w.z, w.w);
            uint2 t;
            t.x = *reinterpret_cast<uint32_t*>(&g0);
            t.y = *reinterpret_cast<uint32_t*>(&g1);
            *reinterpret_cast<uint2*>(&Bs[row][g32 * 4]) = t;
        }
        // Prefetch chunk c+1 (latency hidden by the mma below).
        if (c + 1 < NCHUNK) ldg_chunk(c + 1);
        __syncthreads();    // staged data visible to all warps

        #pragma unroll
        for (int ks = 0; ks < BK / 16; ks++) {
            const int k0 = ks * 16;
            uint32_t afr[4][4];
            #pragma unroll
            for (int mi = 0; mi < 4; mi++) {
                uint32_t addr = smem_u32(&As[k0 + a_kad][a_mad + mi * 16]);
                ldsm_x4_t(afr[mi][0], afr[mi][1], afr[mi][2], afr[mi][3], addr);
            }
            uint32_t bfr[4][2];
            #pragma unroll
            for (int ni = 0; ni < 4; ni++) {
                uint32_t addr = smem_u32(&Bs[k0 + b_kad][warp_n * 32 + ni * 8]);
                ldsm_x2_t(bfr[ni][0], bfr[ni][1], addr);
            }
            #pragma unroll
            for (int mi = 0; mi < 4; mi++)
                #pragma unroll
                for (int ni = 0; ni < 4; ni++)
                    mma_f16(acc[mi][ni][0], acc[mi][ni][1],
                            afr[mi][0], afr[mi][1], afr[mi][2], afr[mi][3],
                            bfr[ni][0], bfr[ni][1]);
        }
        __syncthreads();    // all reads of the buffer done before next STS
    }

    // -------- norm reduction (reuse tile smem as scratch) --------
    #pragma unroll
    for (int i = 0; i < 4; i++) {
        nred[g32 * 4 + i][mrow] = npA[i];          // tensor A: slots 0..127
        nred[128 + g32 * 4 + i][mrow] = npB[i];    // tensor B: slots 128..255
    }
    __syncthreads();
    {
        int t  = tid >> 7;           // 0 = A, 1 = B
        int px = tid & 127;
        float s = 0.f;
        #pragma unroll
        for (int mm = 0; mm < 8; mm++) s += nred[t * 128 + px][mm];
        if (t == 0) s_normA[px] = s; else s_normB[px] = s;
    }
    __syncthreads();

    // --------------------------- fused epilogue ---------------------------
    const int g  = lane >> 2;
    const int tg = lane & 3;
    const int base = n * HW;

    float rn2[4][2]; int rm2[4][2];
    #pragma unroll
    for (int mi = 0; mi < 4; mi++) {
        int rl = warp_m * 64 + mi * 16 + g;
        rn2[mi][0] = s_normA[rl];     rm2[mi][0] = RM[base + p0 + rl];
        rn2[mi][1] = s_normA[rl + 8]; rm2[mi][1] = RM[base + p0 + rl + 8];
    }
    float in2[4][2]; int im2[4][2];
    #pragma unroll
    for (int ni = 0; ni < 4; ni++) {
        int cl = warp_n * 32 + ni * 8 + tg * 2;
        in2[ni][0] = s_normB[cl];     im2[ni][0] = IM[base + q0 + cl];
        in2[ni][1] = s_normB[cl + 1]; im2[ni][1] = IM[base + q0 + cl + 1];
    }

    // Pass 1: min dist (recompute in pass 2 — saves 64 registers).
    float mind = 1e30f;
    #pragma unroll
    for (int mi = 0; mi < 4; mi++)
        #pragma unroll
        for (int ni = 0; ni < 4; ni++) {
            float2 lo = __half22float2(*reinterpret_cast<__half2*>(&acc[mi][ni][0]));
            float2 hi = __half22float2(*reinterpret_cast<__half2*>(&acc[mi][ni][1]));
            mind = fminf(mind, rn2[mi][0] + in2[ni][0] - 2.0f * lo.x);
            mind = fminf(mind, rn2[mi][0] + in2[ni][1] - 2.0f * lo.y);
            mind = fminf(mind, rn2[mi][1] + in2[ni][0] - 2.0f * hi.x);
            mind = fminf(mind, rn2[mi][1] + in2[ni][1] - 2.0f * hi.y);
        }
    const bool fast = __all_sync(0xffffffffu, mind > 18.0f);

    float rowS[4][2], rowM[4][2], colS[4][2], colM[4][2];
    #pragma unroll
    for (int i = 0; i < 4; i++)
        #pragma unroll
        for (int j = 0; j < 2; j++) {
            rowS[i][j] = 0.f; rowM[i][j] = 0.f;
            colS[i][j] = 0.f; colM[i][j] = 0.f;
        }

    if (fast) {
        // Exact: dist > 18 => expf(-dist) < 2^-25 => expf(e1/10) == 1.0f in fp32.
        #pragma unroll
        for (int mi = 0; mi < 4; mi++)
            #pragma unroll
            for (int ni = 0; ni < 4; ni++)
                #pragma unroll
                for (int r = 0; r < 4; r++) {
                    int ri = r >> 1, ci = r & 1;
                    if (rm2[mi][ri] == im2[ni][ci]) {
                        rowM[mi][ri] += 1.0f;
                        colM[ni][ci] += 1.0f;
                    }
                }
        #pragma unroll
        for (int i = 0; i < 4; i++) {
            rowS[i][0] = 8.0f; rowS[i][1] = 8.0f;
            colS[i][0] = 8.0f; colS[i][1] = 8.0f;
        }
    } else {
        #pragma unroll
        for (int mi = 0; mi < 4; mi++)
            #pragma unroll
            for (int ni = 0; ni < 4; ni++) {
                float2 lo = __half22float2(*reinterpret_cast<__half2*>(&acc[mi][ni][0]));
                float2 hi = __half22float2(*reinterpret_cast<__half2*>(&acc[mi][ni][1]));
                float d[4];
                d[0] = rn2[mi][0] + in2[ni][0] - 2.0f * lo.x;
                d[1] = rn2[mi][0] + in2[ni][1] - 2.0f * lo.y;
                d[2] = rn2[mi][1] + in2[ni][0] - 2.0f * hi.x;
                d[3] = rn2[mi][1] + in2[ni][1] - 2.0f * hi.y;
                #pragma unroll
                for (int r = 0; r < 4; r++) {
                    int ri = r >> 1, ci = r & 1;
                    float logit = (d[r] > 18.0f) ? 1.0f : __expf(__expf(-d[r]) * 0.1f);
                    rowS[mi][ri] += logit;
                    colS[ni][ci] += logit;
                    if (rm2[mi][ri] == im2[ni][ci]) {
                        rowM[mi][ri] += logit;
                        colM[ni][ci] += logit;
                    }
                }
            }
    }

    // Row reduce across tg: xor 1, 2.
    #pragma unroll
    for (int mi = 0; mi < 4; mi++)
        #pragma unroll
        for (int ri = 0; ri < 2; ri++) {
            float v = rowS[mi][ri], m = rowM[mi][ri];
            v += __shfl_xor_sync(0xffffffffu, v, 1);
            v += __shfl_xor_sync(0xffffffffu, v, 2);
            m += __shfl_xor_sync(0xffffffffu, m, 1);
            m += __shfl_xor_sync(0xffffffffu, m, 2);
            if (tg == 0) {
                int r = p0 + warp_m * 64 + mi * 16 + g + ri * 8;
                atomicAdd(&g_rowL [base + r], v);
                atomicAdd(&g_rowLM[base + r], m);
            }
        }

    // Col reduce across g: xor 4, 8, 16.
    #pragma unroll
    for (int ni = 0; ni < 4; ni++)
        #pragma unroll
        for (int ci = 0; ci < 2; ci++) {
            float v = colS[ni][ci], m = colM[ni][ci];
            v += __shfl_xor_sync(0xffffffffu, v, 4);
            v += __shfl_xor_sync(0xffffffffu, v, 8);
            v += __shfl_xor_sync(0xffffffffu, v, 16);
            m += __shfl_xor_sync(0xffffffffu, m, 4);
            m += __shfl_xor_sync(0xffffffffu, m, 8);
            m += __shfl_xor_sync(0xffffffffu, m, 16);
            if (g == 0) {
                int c = q0 + warp_n * 32 + ni * 8 + tg * 2 + ci;
                atomicAdd(&g_colL [base + c], v);
                atomicAdd(&g_colLM[base + c], m);
            }
        }
}

// ---------------------------------------------------------------------------
// reduce: masked -log sums across 64 blocks -> out. Self-cleaning: zeroes the
// accumulators after reading and resets tot/cnt/ctr, so the next call (and
// the first, via static zero-init) always starts from a clean state.
// ---------------------------------------------------------------------------
__global__ __launch_bounds__(256)
void reduce_kernel(const int* __restrict__ RM, const int* __restrict__ IM,
                   float* __restrict__ out)
{
    __shared__ float s_t[256];
    __shared__ float s_c[256];
    __shared__ unsigned int s_rank;
    int tid = threadIdx.x;
    int j = blockIdx.x * 128 + (tid & 127);      // 64 blocks x 128 = 8192
    bool isRow = tid < 128;

    float tot = 0.f, cnt = 0.f;
    if (isRow) {
        float l = g_rowL[j] + 1e-6f;
        float v = g_rowLM[j] / l;
        if (RM[j] > 0 && v != 0.0f) { tot = -__logf(v); cnt = 1.f; }
        g_rowL[j] = 0.f; g_rowLM[j] = 0.f;       // clean for next call
    } else {
        float l = g_colL[j] + 1e-6f;
        float v = g_colLM[j] / l;
        if (IM[j] > 0 && v != 0.0f) { tot = -__logf(v); cnt = 1.f; }
        g_colL[j] = 0.f; g_colLM[j] = 0.f;       // clean for next call
    }
    s_t[tid] = tot; s_c[tid] = cnt;
    __syncthreads();
    for (int s = 128; s > 0; s >>= 1) {
        if (tid < s) { s_t[tid] += s_t[tid + s]; s_c[tid] += s_c[tid + s]; }
        __syncthreads();
    }
    if (tid == 0) {
        atomicAdd(&g_tot, s_t[0]);
        atomicAdd(&g_cnt, s_c[0]);
        __threadfence();
        s_rank = atomicAdd(&g_rctr, 1u);
    }
    __syncthreads();
    if (s_rank == RBLK - 1 && tid == 0) {
        out[0] = g_tot / g_cnt;
        g_tot = 0.f; g_cnt = 0.f; g_rctr = 0u;   // clean for next call
    }
}

// ---------------------------------------------------------------------------
extern "C" void kernel_launch(void* const* d_in, const int* in_sizes, int n_in,
                              void* d_out, int out_size)
{
    const float* R  = (const float*)d_in[0];   // rgb_map  (N,C,H,W) fp32
    const float* I  = (const float*)d_in[1];   // ir_map   (N,C,H,W) fp32
    const int*   RM = (const int*)  d_in[2];   // rgb_mask (N,H,W)   int32
    const int*   IM = (const int*)  d_in[3];   // ir_mask  (N,H,W)   int32
    float* out = (float*)d_out;

    dim3 grid(HW / BN, HW / BM, NB);           // (8, 8, 8) = 512 CTAs
    tile_kernel<<<grid, 256>>>(R, I, RM, IM);

    reduce_kernel<<<RBLK, 256>>>(RM, IM, out);
}